// round 4
// baseline (speedup 1.0000x reference)
#include <cuda_runtime.h>

typedef unsigned long long u64;

// Problem constants
#define TT    4096
#define FF    9
#define NSEQ  2048
#define L1    2049
#define L2    1025
#define L3    513

// Tiling
#define V3      40
#define NTILES  13              // 12*40=480, last tile 33
#define IN_LEN  (8*V3+14)       // 334

// Row strides in u64 (pair) units
#define P0   339                // h0 dup rows, reads <=337
#define P1   173                // s1 dup rows, writes <=167, reads <=169
#define P2   85                 // s2 dup rows, writes <=83, reads <=81
#define W1S  29                 // weight pair-row strides (odd -> conflict-free)
#define W2S  49
#define W3S  97

// SMEM float offsets (all even -> 8B aligned)
#define OFF_H0   0
#define OFF_S1   (OFF_H0 + 9*2*P0)      // 6102
#define OFF_S2   (OFF_S1 + 16*2*P1)     // +5536
#define OFF_W1   (OFF_S2 + 32*2*P2)     // +5440
#define OFF_W2   (OFF_W1 + 8*2*W1S)     // +464
#define OFF_W3   (OFF_W2 + 16*2*W2S)    // +1568
#define OFF_SB   (OFF_W3 + 8*2*W3S)     // +1552
#define OFF_FACC (OFF_SB + 64)
#define SM_FLOATS (OFF_FACC + 2*320)    // 21366
#define SMEM_BYTES (SM_FLOATS * 4)

__device__ __forceinline__ u64 ffma2(u64 a, u64 b, u64 c) {
    u64 d;
    asm("fma.rn.f32x2 %0, %1, %2, %3;" : "=l"(d) : "l"(a), "l"(b), "l"(c));
    return d;
}
__device__ __forceinline__ u64 pack2(float lo, float hi) {
    u64 v;
    asm("mov.b64 %0, {%1, %2};" : "=l"(v) : "f"(lo), "f"(hi));
    return v;
}
__device__ __forceinline__ void unpack2(u64 v, float& lo, float& hi) {
    asm("mov.b64 {%0, %1}, %2;" : "=f"(lo), "=f"(hi) : "l"(v));
}

__device__ float g_feat[NSEQ * 16];

__global__ __launch_bounds__(256) void cnn_main(
    const float* __restrict__ x,
    const float* __restrict__ w1, const float* __restrict__ b1,
    const float* __restrict__ w2, const float* __restrict__ b2,
    const float* __restrict__ w3, const float* __restrict__ b3)
{
    extern __shared__ float sm[];
    u64* h0p = (u64*)(sm + OFF_H0);     // [9][P0]   dup (x,x)
    u64* s1p = (u64*)(sm + OFF_S1);     // [16][P1]  dup (v,v)
    u64* s2p = (u64*)(sm + OFF_S2);     // [32][P2]  dup (v,v)
    u64* w1p = (u64*)(sm + OFF_W1);     // [8][W1S]  (w_co0, w_co1)
    u64* w2p = (u64*)(sm + OFF_W2);     // [16][W2S]
    u64* w3p = (u64*)(sm + OFF_W3);     // [8][W3S]
    float* sb   = sm + OFF_SB;          // b1[0:16) b2[16:48) b3[48:64)
    u64*  faccp = (u64*)(sm + OFF_FACC);// [320] per-item (ch0,ch1) partial sums

    const int tid = threadIdx.x;
    const int n   = blockIdx.x;
    const float* xin = x + (size_t)n * (TT * FF);

    // Zero all smem once (provides persistent zero padding)
    for (int i = tid; i < SM_FLOATS; i += 256) sm[i] = 0.f;
    __syncthreads();

    // Weights: channel-pair interleaved. w*[co][ci][k] -> pair row co>>1, comp co&1
    for (int i = tid; i < 16*27; i += 256) {
        int co = i / 27, r = i - co*27;
        sm[OFF_W1 + ((co>>1)*W1S + r)*2 + (co&1)] = w1[i];
    }
    for (int i = tid; i < 32*48; i += 256) {
        int co = i / 48, r = i - co*48;
        sm[OFF_W2 + ((co>>1)*W2S + r)*2 + (co&1)] = w2[i];
    }
    for (int i = tid; i < 16*96; i += 256) {
        int co = i / 96, r = i - co*96;
        sm[OFF_W3 + ((co>>1)*W3S + r)*2 + (co&1)] = w3[i];
    }
    if (tid < 16)      sb[tid] = b1[tid];
    else if (tid < 48) sb[tid] = b2[tid-16];
    else if (tid < 64) sb[tid] = b3[tid-48];
    __syncthreads();

    for (int tile = 0; tile < NTILES; ++tile) {
        const int va  = tile * V3;
        const int t0  = 8*va - 14;
        const int u1b = 4*va - 6;
        const int u2b = 2*va - 2;

        // ---- Phase A: coalesced load + transpose + duplicate ----
        for (int idx = tid; idx < IN_LEN*FF; idx += 256) {
            int tl = idx / FF;
            int ci = idx - tl*FF;
            int t  = t0 + tl;
            float v = 0.f;
            if (t >= 0 && t < TT) v = xin[t*FF + ci];
            h0p[ci*P0 + tl] = pack2(v, v);
        }
        __syncthreads();

        // ---- Phase B: stage1 conv(9->16) + relu + pool2 ----
        // item: pair(8) low bits, quad(42) high -> 336 items
        for (int it = 0; it < 2; ++it) {
            int item = tid + it*256;
            if (item >= 336) break;
            int pr  = item & 7;
            int q   = item >> 3;        // 0..41
            int ul0 = q * 4;
            u64 acc[8];
            #pragma unroll
            for (int p = 0; p < 8; ++p) acc[p] = 0ULL;
            const u64* wp = w1p + pr*W1S;
            const u64* hp = h0p + 8*q;
            #pragma unroll 3
            for (int ci = 0; ci < 9; ++ci) {
                u64 P[10];
                #pragma unroll
                for (int j = 0; j < 10; ++j) P[j] = hp[j];
                u64 W0 = wp[0], W1 = wp[1], W2 = wp[2];
                #pragma unroll
                for (int p = 0; p < 8; ++p) {
                    acc[p] = ffma2(W0, P[p],   acc[p]);
                    acc[p] = ffma2(W1, P[p+1], acc[p]);
                    acc[p] = ffma2(W2, P[p+2], acc[p]);
                }
                wp += 3; hp += P0;
            }
            float b0 = sb[2*pr], b1v = sb[2*pr+1];
            u64* r0 = s1p + (2*pr)*P1;
            u64* r1 = r0 + P1;
            #pragma unroll
            for (int q4 = 0; q4 < 4; ++q4) {
                float a0, a1, c0, c1;
                unpack2(acc[2*q4],   a0, a1);
                unpack2(acc[2*q4+1], c0, c1);
                int ul  = ul0 + q4;
                int ug1 = u1b + ul;
                bool valid = (ug1 >= 0) && (ug1 < L1);
                float v0 = fmaxf(fmaxf(a0, c0) + b0, 0.f);
                float v1 = fmaxf(fmaxf(a1, c1) + b1v, 0.f);
                if (!valid) { v0 = 0.f; v1 = 0.f; }
                r0[ul] = pack2(v0, v0);
                r1[ul] = pack2(v1, v1);
            }
        }
        __syncthreads();

        // ---- Phase C: stage2 conv(16->32) + relu + pool2 ----
        // item: pair(16) low, quad(21) high -> 336 items
        for (int it = 0; it < 2; ++it) {
            int item = tid + it*256;
            if (item >= 336) break;
            int pr  = item & 15;
            int q   = item >> 4;        // 0..20
            int ul0 = q * 4;
            u64 acc[8];
            #pragma unroll
            for (int p = 0; p < 8; ++p) acc[p] = 0ULL;
            const u64* wp = w2p + pr*W2S;
            const u64* hp = s1p + 8*q;
            #pragma unroll 2
            for (int ci = 0; ci < 16; ++ci) {
                u64 P[10];
                #pragma unroll
                for (int j = 0; j < 10; ++j) P[j] = hp[j];
                u64 W0 = wp[0], W1 = wp[1], W2 = wp[2];
                #pragma unroll
                for (int p = 0; p < 8; ++p) {
                    acc[p] = ffma2(W0, P[p],   acc[p]);
                    acc[p] = ffma2(W1, P[p+1], acc[p]);
                    acc[p] = ffma2(W2, P[p+2], acc[p]);
                }
                wp += 3; hp += P1;
            }
            float b0 = sb[16 + 2*pr], b1v = sb[16 + 2*pr + 1];
            u64* r0 = s2p + (2*pr)*P2;
            u64* r1 = r0 + P2;
            #pragma unroll
            for (int q4 = 0; q4 < 4; ++q4) {
                float a0, a1, c0, c1;
                unpack2(acc[2*q4],   a0, a1);
                unpack2(acc[2*q4+1], c0, c1);
                int ul  = ul0 + q4;
                int ug2 = u2b + ul;
                bool valid = (ug2 >= 0) && (ug2 < L2);
                float v0 = fmaxf(fmaxf(a0, c0) + b0, 0.f);
                float v1 = fmaxf(fmaxf(a1, c1) + b1v, 0.f);
                if (!valid) { v0 = 0.f; v1 = 0.f; }
                r0[ul] = pack2(v0, v0);
                r1[ul] = pack2(v1, v1);
            }
        }
        __syncthreads();

        // ---- Phase D: stage3 conv(32->16) + relu + pool2 + mean-acc ----
        // item: pair(8) low, pooled pos v(40) high -> 320 items
        for (int it = 0; it < 2; ++it) {
            int item = tid + it*256;
            if (item >= 320) break;
            int pr = item & 7;
            int v  = item >> 3;         // 0..39
            u64 a0 = 0ULL, a1 = 0ULL;
            const u64* wp = w3p + pr*W3S;
            const u64* hp = s2p + 2*v;
            #pragma unroll 4
            for (int ci = 0; ci < 32; ++ci) {
                u64 Q0 = hp[0], Q1 = hp[1], Q2 = hp[2], Q3 = hp[3];
                u64 W0 = wp[0], W1 = wp[1], W2 = wp[2];
                a0 = ffma2(W0, Q0, a0);
                a0 = ffma2(W1, Q1, a0);
                a0 = ffma2(W2, Q2, a0);
                a1 = ffma2(W0, Q1, a1);
                a1 = ffma2(W1, Q2, a1);
                a1 = ffma2(W2, Q3, a1);
                wp += 3; hp += P2;
            }
            float x0, x1, y0, y1;
            unpack2(a0, x0, x1);
            unpack2(a1, y0, y1);
            float b0 = sb[48 + 2*pr], b1v = sb[48 + 2*pr + 1];
            float r0 = fmaxf(fmaxf(x0, y0) + b0, 0.f);
            float r1 = fmaxf(fmaxf(x1, y1) + b1v, 0.f);
            if (va + v < L3) {
                float s0, s1v;
                unpack2(faccp[item], s0, s1v);
                faccp[item] = pack2(s0 + r0, s1v + r1);
            }
        }
        __syncthreads();
    }

    // ---- mean over L3=513 positions ----
    if (tid < 16) {
        int pr = tid >> 1, comp = tid & 1;
        float s = 0.f;
        #pragma unroll
        for (int k = 0; k < 40; ++k)
            s += sm[OFF_FACC + (pr + 8*k)*2 + comp];
        g_feat[n*16 + tid] = s * (1.0f / 513.0f);
    }
}

// Final: feat [B, J*16=128] -> maxpool k=3 -> [B, 42]
__global__ void final_pool(float* __restrict__ out)
{
    int i = blockIdx.x * blockDim.x + threadIdx.x;
    if (i >= 256*42) return;
    int b = i / 42;
    int g = i - b*42;
    float m = -1e30f;
    #pragma unroll
    for (int e3 = 0; e3 < 3; ++e3) {
        int e = 3*g + e3;
        int j = e >> 4;
        int c = e & 15;
        m = fmaxf(m, g_feat[(b*8 + j)*16 + c]);
    }
    out[i] = m;
}

extern "C" void kernel_launch(void* const* d_in, const int* in_sizes, int n_in,
                              void* d_out, int out_size)
{
    (void)in_sizes; (void)n_in; (void)out_size;
    const float* x  = (const float*)d_in[0];
    const float* w1 = (const float*)d_in[1];
    const float* b1 = (const float*)d_in[2];
    const float* w2 = (const float*)d_in[3];
    const float* b2 = (const float*)d_in[4];
    const float* w3 = (const float*)d_in[5];
    const float* b3 = (const float*)d_in[6];
    float* out = (float*)d_out;

    cudaFuncSetAttribute(cnn_main, cudaFuncAttributeMaxDynamicSharedMemorySize, SMEM_BYTES);
    cnn_main<<<NSEQ, 256, SMEM_BYTES>>>(x, w1, b1, w2, b2, w3, b3);
    final_pool<<<42, 256>>>(out);
}

// round 6
// speedup vs baseline: 1.0929x; 1.0929x over previous
#include <cuda_runtime.h>
#include <cuda_bf16.h>

typedef unsigned int       u32;
typedef unsigned long long u64;

#define NSEQ 2048
#define TT   4096
#define V3T  60
#define NT   9

// byte strides (all ≡ 16 mod 128, odd multiple of 16 -> conflict-free ldmatrix)
#define SA1 144
#define SA2 208
#define SA3 400
#define SB1 144
#define SB2 208
#define SB3 400

// byte offsets inside A/B arena
#define OA1 0u
#define OA2 73728u            // 512*144
#define OA3 126976u           // +256*208
#define OB1 178176u           // +128*400
#define OB2 180480u           // +16*144
#define OB3 187136u           // +32*208
#define ABSZ 193536u          // +16*400

#define SMEM_BYTES (4096 + ABSZ)

__device__ float g_feat[NSEQ * 16];

// ---------- helpers ----------
__device__ __forceinline__ u32 smem_u32p(const void* p) {
    u32 a;
    asm("{ .reg .u64 t; cvta.to.shared.u64 t, %1; cvt.u32.u64 %0, t; }" : "=r"(a) : "l"(p));
    return a;
}
__device__ __forceinline__ void sts32(u32 a, u32 v) {
    asm volatile("st.shared.b32 [%0], %1;" :: "r"(a), "r"(v) : "memory");
}
__device__ __forceinline__ u32 lds32(u32 a) {
    u32 v;
    asm volatile("ld.shared.b32 %0, [%1];" : "=r"(v) : "r"(a));
    return v;
}
__device__ __forceinline__ u32 dupbf(float v) {
    u32 r;
    asm("cvt.rn.bf16x2.f32 %0, %1, %1;" : "=r"(r) : "f"(v));
    return r;
}
__device__ __forceinline__ u32 wsplit(float v) {
    __nv_bfloat16 h = __float2bfloat16_rn(v);
    float lo = v - __bfloat162float(h);
    return (u32)__bfloat16_as_ushort(h) | ((u32)__bfloat16_as_ushort(__float2bfloat16_rn(lo)) << 16);
}
__device__ __forceinline__ void lda4(u32 addr, u32& a0, u32& a1, u32& a2, u32& a3) {
    asm volatile("ldmatrix.sync.aligned.m8n8.x4.shared.b16 {%0,%1,%2,%3}, [%4];"
                 : "=r"(a0), "=r"(a1), "=r"(a2), "=r"(a3) : "r"(addr));
}
__device__ __forceinline__ void mma16816(float* d, u32 a0, u32 a1, u32 a2, u32 a3, u32 b0, u32 b1) {
    asm volatile(
        "mma.sync.aligned.m16n8k16.row.col.f32.bf16.bf16.f32 "
        "{%0,%1,%2,%3}, {%4,%5,%6,%7}, {%8,%9}, {%0,%1,%2,%3};"
        : "+f"(d[0]), "+f"(d[1]), "+f"(d[2]), "+f"(d[3])
        : "r"(a0), "r"(a1), "r"(a2), "r"(a3), "r"(b0), "r"(b1));
}

__global__ __launch_bounds__(256, 1) void cnn_main(
    const float* __restrict__ x,
    const float* __restrict__ w1, const float* __restrict__ b1,
    const float* __restrict__ w2, const float* __restrict__ b2,
    const float* __restrict__ w3, const float* __restrict__ b3)
{
    extern __shared__ float smf[];
    const int tid = threadIdx.x;
    const int w_  = tid >> 5;
    const int l   = tid & 31;
    const int g   = l >> 2;            // mma group id
    const int t4  = l & 3;             // thread-in-group
    const bool act = ((g & 1) == 0);   // even-row lanes own pooled outputs
    const int n   = blockIdx.x;
    const float* xin = x + (size_t)n * (TT * 9);

    float* sb   = smf;                 // 64 biases
    float* facc = smf + 64;            // [60][16]
    const u32 abase = smem_u32p(smf) + 4096u;

    // zero arena (pads stay zero forever; stale rows finite) + facc
    for (u32 o = 4u * tid; o < ABSZ; o += 1024u) sts32(abase + o, 0u);
    for (int i = tid; i < 960; i += 256) facc[i] = 0.f;
    if (tid < 16)      sb[tid] = b1[tid];
    else if (tid < 48) sb[tid] = b2[tid - 16];
    else if (tid < 64) sb[tid] = b3[tid - 48];

    // B tiles: [n][k2] rows, slot-pair (w_hi, w_lo)
    for (int i = tid; i < 16 * 27; i += 256) {
        int co = i / 27, j = i - co * 27, ci = j / 3, kk = j - ci * 3;
        sts32(abase + OB1 + (u32)(co * SB1 + (ci + 9 * kk) * 4), wsplit(w1[i]));
    }
    for (int i = tid; i < 32 * 48; i += 256) {
        int co = i / 48, j = i - co * 48, ci = j / 3, kk = j - ci * 3;
        sts32(abase + OB2 + (u32)(co * SB2 + (ci + 16 * kk) * 4), wsplit(w2[i]));
    }
    for (int i = tid; i < 16 * 96; i += 256) {
        int co = i / 96, j = i - co * 96, ci = j / 3, kk = j - ci * 3;
        sts32(abase + OB3 + (u32)(co * SB3 + (ci + 32 * kk) * 4), wsplit(w3[i]));
    }
    __syncthreads();

    for (int tile = 0; tile < NT; ++tile) {
        const int va   = tile * V3T;
        const int u1b  = 4 * va - 6;
        const int u2b  = 2 * va - 2;
        const int tb   = 8 * va - 14;

        // ---- build A1: rows r in [0,512), pair(ci+9kk) = x[tb + r + kk] ----
        for (int idx = tid; idx < 514 * 9; idx += 256) {
            int tl = idx / 9, ci = idx - tl * 9;
            int t  = tb + tl;
            float v = ((unsigned)t < (unsigned)TT) ? xin[t * 9 + ci] : 0.f;
            u32 d = dupbf(v);
            #pragma unroll
            for (int kk = 0; kk < 3; ++kk) {
                int r = tl - kk;
                if ((unsigned)r < 512u)
                    sts32(abase + OA1 + (u32)(r * SA1 + (ci + 9 * kk) * 4), d);
            }
        }
        __syncthreads();

        // ================= stage 1: 512 rows, N=16, 4 ksteps =================
        {
            float acc[4][2][4];
            #pragma unroll
            for (int mi = 0; mi < 4; ++mi)
                #pragma unroll
                for (int nf = 0; nf < 2; ++nf)
                    #pragma unroll
                    for (int q = 0; q < 4; ++q) acc[mi][nf][q] = 0.f;

            #pragma unroll
            for (int ks = 0; ks < 4; ++ks) {
                #pragma unroll
                for (int mi = 0; mi < 4; ++mi) {
                    int row = 64 * w_ + 16 * mi + (l & 7) + 8 * ((l >> 3) & 1);
                    u32 aaddr = abase + OA1 + (u32)(row * SA1 + ks * 32 + ((l >> 4) & 1) * 16);
                    u32 a0, a1, a2, a3;
                    lda4(aaddr, a0, a1, a2, a3);
                    #pragma unroll
                    for (int nf = 0; nf < 2; ++nf) {
                        u32 ba = abase + OB1 + (u32)((nf * 8 + g) * SB1 + ks * 32 + t4 * 4);
                        mma16816(acc[mi][nf], a0, a1, a2, a3, lds32(ba), lds32(ba + 16));
                    }
                }
            }
            // epilogue: pool(shfl^4) -> relu(bias) -> scatter A2
            #pragma unroll
            for (int mi = 0; mi < 4; ++mi) {
                #pragma unroll
                for (int nf = 0; nf < 2; ++nf) {
                    float p0 = fmaxf(acc[mi][nf][0], __shfl_xor_sync(0xffffffffu, acc[mi][nf][0], 4));
                    float p1 = fmaxf(acc[mi][nf][1], __shfl_xor_sync(0xffffffffu, acc[mi][nf][1], 4));
                    float p2 = fmaxf(acc[mi][nf][2], __shfl_xor_sync(0xffffffffu, acc[mi][nf][2], 4));
                    float p3 = fmaxf(acc[mi][nf][3], __shfl_xor_sync(0xffffffffu, acc[mi][nf][3], 4));
                    if (act) {
                        int ua = 32 * w_ + 8 * mi + (g >> 1);
                        int j0 = nf * 8 + 2 * t4;
                        #pragma unroll
                        for (int s = 0; s < 4; ++s) {
                            int u = ua + ((s >> 1) ? 4 : 0);
                            int j = j0 + (s & 1);
                            float p = (s == 0) ? p0 : (s == 1) ? p1 : (s == 2) ? p2 : p3;
                            int gg = u + u1b;
                            float y = (gg >= 0 && gg < 2049) ? fmaxf(p + sb[j], 0.f) : 0.f;
                            u32 d = dupbf(y);
                            #pragma unroll
                            for (int kk = 0; kk < 3; ++kk) {
                                int c2 = u - kk;
                                if ((unsigned)c2 < 244u)
                                    sts32(abase + OA2 + (u32)(c2 * SA2 + (j + 16 * kk) * 4), d);
                            }
                        }
                    }
                }
            }
        }
        __syncthreads();

        // ================= stage 2: 256 rows, N=32, 6 ksteps =================
        {
            float acc[2][4][4];
            #pragma unroll
            for (int mi = 0; mi < 2; ++mi)
                #pragma unroll
                for (int nf = 0; nf < 4; ++nf)
                    #pragma unroll
                    for (int q = 0; q < 4; ++q) acc[mi][nf][q] = 0.f;

            #pragma unroll
            for (int ks = 0; ks < 6; ++ks) {
                #pragma unroll
                for (int mi = 0; mi < 2; ++mi) {
                    int row = 32 * w_ + 16 * mi + (l & 7) + 8 * ((l >> 3) & 1);
                    u32 aaddr = abase + OA2 + (u32)(row * SA2 + ks * 32 + ((l >> 4) & 1) * 16);
                    u32 a0, a1, a2, a3;
                    lda4(aaddr, a0, a1, a2, a3);
                    #pragma unroll
                    for (int nf = 0; nf < 4; ++nf) {
                        u32 ba = abase + OB2 + (u32)((nf * 8 + g) * SB2 + ks * 32 + t4 * 4);
                        mma16816(acc[mi][nf], a0, a1, a2, a3, lds32(ba), lds32(ba + 16));
                    }
                }
            }
            #pragma unroll
            for (int mi = 0; mi < 2; ++mi) {
                #pragma unroll
                for (int nf = 0; nf < 4; ++nf) {
                    float p0 = fmaxf(acc[mi][nf][0], __shfl_xor_sync(0xffffffffu, acc[mi][nf][0], 4));
                    float p1 = fmaxf(acc[mi][nf][1], __shfl_xor_sync(0xffffffffu, acc[mi][nf][1], 4));
                    float p2 = fmaxf(acc[mi][nf][2], __shfl_xor_sync(0xffffffffu, acc[mi][nf][2], 4));
                    float p3 = fmaxf(acc[mi][nf][3], __shfl_xor_sync(0xffffffffu, acc[mi][nf][3], 4));
                    if (act) {
                        int ua = 16 * w_ + 8 * mi + (g >> 1);
                        int j0 = nf * 8 + 2 * t4;
                        #pragma unroll
                        for (int s = 0; s < 4; ++s) {
                            int u = ua + ((s >> 1) ? 4 : 0);
                            int j = j0 + (s & 1);
                            float p = (s == 0) ? p0 : (s == 1) ? p1 : (s == 2) ? p2 : p3;
                            int gg = u + u2b;
                            float y = (gg >= 0 && gg < 1025) ? fmaxf(p + sb[16 + j], 0.f) : 0.f;
                            u32 d = dupbf(y);
                            #pragma unroll
                            for (int kk = 0; kk < 3; ++kk) {
                                int c3 = u - kk;
                                if ((unsigned)c3 < 120u)
                                    sts32(abase + OA3 + (u32)(c3 * SA3 + (j + 32 * kk) * 4), d);
                            }
                        }
                    }
                }
            }
        }
        __syncthreads();

        // ================= stage 3: 128 rows, N=16, 12 ksteps =================
        {
            float acc[2][4];
            #pragma unroll
            for (int nf = 0; nf < 2; ++nf)
                #pragma unroll
                for (int q = 0; q < 4; ++q) acc[nf][q] = 0.f;

            #pragma unroll
            for (int ks = 0; ks < 12; ++ks) {
                int row = 16 * w_ + (l & 7) + 8 * ((l >> 3) & 1);
                u32 aaddr = abase + OA3 + (u32)(row * SA3 + ks * 32 + ((l >> 4) & 1) * 16);
                u32 a0, a1, a2, a3;
                lda4(aaddr, a0, a1, a2, a3);
                #pragma unroll
                for (int nf = 0; nf < 2; ++nf) {
                    u32 ba = abase + OB3 + (u32)((nf * 8 + g) * SB3 + ks * 32 + t4 * 4);
                    mma16816(acc[nf], a0, a1, a2, a3, lds32(ba), lds32(ba + 16));
                }
            }
            #pragma unroll
            for (int nf = 0; nf < 2; ++nf) {
                float p0 = fmaxf(acc[nf][0], __shfl_xor_sync(0xffffffffu, acc[nf][0], 4));
                float p1 = fmaxf(acc[nf][1], __shfl_xor_sync(0xffffffffu, acc[nf][1], 4));
                float p2 = fmaxf(acc[nf][2], __shfl_xor_sync(0xffffffffu, acc[nf][2], 4));
                float p3 = fmaxf(acc[nf][3], __shfl_xor_sync(0xffffffffu, acc[nf][3], 4));
                if (act) {
                    int va_ = 8 * w_ + (g >> 1);
                    int j0  = nf * 8 + 2 * t4;
                    #pragma unroll
                    for (int s = 0; s < 4; ++s) {
                        int v = va_ + ((s >> 1) ? 4 : 0);
                        int j = j0 + (s & 1);
                        float p = (s == 0) ? p0 : (s == 1) ? p1 : (s == 2) ? p2 : p3;
                        if (v < 60 && va + v < 513) {
                            float y = fmaxf(p + sb[48 + j], 0.f);
                            facc[v * 16 + j] += y;
                        }
                    }
                }
            }
        }
        __syncthreads();
    }

    // mean over 513 pooled positions
    if (tid < 16) {
        float s = 0.f;
        for (int v = 0; v < 60; ++v) s += facc[v * 16 + tid];
        g_feat[n * 16 + tid] = s * (1.0f / 513.0f);
    }
}

// Final: feat [B, J*16=128] -> maxpool k=3 -> [B, 42]
__global__ void final_pool(float* __restrict__ out)
{
    int i = blockIdx.x * blockDim.x + threadIdx.x;
    if (i >= 256 * 42) return;
    int b = i / 42, gg = i - b * 42;
    float m = -1e30f;
    #pragma unroll
    for (int e3 = 0; e3 < 3; ++e3) {
        int e = 3 * gg + e3;
        m = fmaxf(m, g_feat[(b * 8 + (e >> 4)) * 16 + (e & 15)]);
    }
    out[i] = m;
}

extern "C" void kernel_launch(void* const* d_in, const int* in_sizes, int n_in,
                              void* d_out, int out_size)
{
    (void)in_sizes; (void)n_in; (void)out_size;
    cudaFuncSetAttribute(cnn_main, cudaFuncAttributeMaxDynamicSharedMemorySize, SMEM_BYTES);
    cnn_main<<<NSEQ, 256, SMEM_BYTES>>>(
        (const float*)d_in[0],
        (const float*)d_in[1], (const float*)d_in[2],
        (const float*)d_in[3], (const float*)d_in[4],
        (const float*)d_in[5], (const float*)d_in[6]);
    final_pool<<<42, 256>>>((float*)d_out);
}